// round 4
// baseline (speedup 1.0000x reference)
#include <cuda_runtime.h>

// ============================================================================
// AttentionBlock: GroupNorm -> q,k,v (1x1 conv) -> softmax(q^T k / sqrt(C)) v
//                 -> proj (1x1 conv) -> residual
// B=8, C=512, H=W=64 (N=4096 spatial), 32 groups.
//
// fp32 pipeline with packed f32x2 FMA (FFMA2) SGEMM. On sm_103a, 3-reg FFMA
// is half-rate (rt_SMSP=2); fma.rn.f32x2 recovers the full-width fp32 pipe.
//
// Scratch: several moderate __device__ globals (<= 64 MB each, 320 MB total).
// The attention core (S = q^T k, softmax, ha = v S^T) runs per batch so S is
// a single 64 MB buffer -- it also stays L2-resident (126 MB L2) between the
// S-GEMM, softmax, and AV-GEMM. ha reuses the hn buffer (dead after v GEMM).
// ============================================================================

namespace cfg {
constexpr int BATCH = 8;
constexpr int C     = 512;
constexpr int HW    = 4096;   // 64*64
constexpr int NG    = 32;     // groups
constexpr int CPG   = C / NG; // 16 channels per group
constexpr float EPS   = 1e-5f;
constexpr float SCALE = 0.04419417382415922f; // 1/sqrt(512)

constexpr size_t SZ_CH = (size_t)BATCH * C * HW;  // 16 Mi elems (64 MB)
constexpr size_t SZ_S1 = (size_t)HW * HW;         // 16 Mi elems (64 MB), 1 batch
}

// -------------------- scratch (static device globals; no cudaMalloc) --------
__device__ float g_hn[cfg::SZ_CH];  // 64 MB; reused as ha after v is computed
__device__ float g_q [cfg::SZ_CH];  // 64 MB
__device__ float g_k [cfg::SZ_CH];  // 64 MB
__device__ float g_v [cfg::SZ_CH];  // 64 MB
__device__ float g_S [cfg::SZ_S1];  // 64 MB (single batch)

// -------------------- f32x2 packed helpers ----------------------------------
typedef unsigned long long u64;

__device__ __forceinline__ u64 pack_dup(float x) {
    u64 r;
    asm("mov.b64 %0, {%1, %1};" : "=l"(r) : "f"(x));
    return r;
}
__device__ __forceinline__ void fma2(u64& d, u64 a, u64 b) {
    asm("fma.rn.f32x2 %0, %1, %2, %0;" : "+l"(d) : "l"(a), "l"(b));
}
__device__ __forceinline__ float2 unpack2(u64 v) {
    float lo, hi;
    asm("mov.b64 {%0, %1}, %2;" : "=f"(lo), "=f"(hi) : "l"(v));
    return make_float2(lo, hi);
}

// -------------------- GroupNorm ---------------------------------------------
// One block per (batch, group): reduce mean/var over 16ch x 4096 = 65536 elems.
__global__ __launch_bounds__(512)
void groupnorm_kernel(const float* __restrict__ x,
                      const float* __restrict__ gamma,
                      const float* __restrict__ beta,
                      float* __restrict__ out)
{
    using namespace cfg;
    __shared__ float shs[16], shss[16];
    const int b = blockIdx.x >> 5;
    const int g = blockIdx.x & 31;
    const size_t base = ((size_t)b * C + (size_t)g * CPG) * HW;
    const int n = CPG * HW;  // 65536

    float s = 0.f, ss = 0.f;
    for (int i = threadIdx.x; i < n; i += 512) {
        float v = x[base + i];
        s += v; ss += v * v;
    }
#pragma unroll
    for (int o = 16; o; o >>= 1) {
        s  += __shfl_xor_sync(0xffffffffu, s,  o);
        ss += __shfl_xor_sync(0xffffffffu, ss, o);
    }
    const int w = threadIdx.x >> 5;
    if ((threadIdx.x & 31) == 0) { shs[w] = s; shss[w] = ss; }
    __syncthreads();
    s = 0.f; ss = 0.f;
#pragma unroll
    for (int i = 0; i < 16; i++) { s += shs[i]; ss += shss[i]; }

    const float mean = s / n;
    const float var  = ss / n - mean * mean;
    const float rstd = rsqrtf(var + EPS);

    for (int i = threadIdx.x; i < n; i += 512) {
        const int c = g * CPG + (i >> 12);  // i / HW
        out[base + i] = (x[base + i] - mean) * rstd * gamma[c] + beta[c];
    }
}

// -------------------- Row softmax over 4096 ---------------------------------
// One block per row; values cached in registers (16/thread) to avoid a reread.
__global__ __launch_bounds__(256)
void softmax_kernel(float* __restrict__ S)
{
    using namespace cfg;
    __shared__ float shm[8];   // warp maxes
    __shared__ float shsum[8]; // warp sums
    const size_t row = blockIdx.x;
    float* p = S + row * (size_t)HW;
    const int t = threadIdx.x;

    float vals[16];
    float m = -3.4e38f;
#pragma unroll
    for (int i = 0; i < 16; i++) {
        vals[i] = p[t + i * 256];
        m = fmaxf(m, vals[i]);
    }
#pragma unroll
    for (int o = 16; o; o >>= 1) m = fmaxf(m, __shfl_xor_sync(0xffffffffu, m, o));
    if ((t & 31) == 0) shm[t >> 5] = m;
    __syncthreads();
    m = shm[0];
#pragma unroll
    for (int w = 1; w < 8; w++) m = fmaxf(m, shm[w]);

    float s = 0.f;
#pragma unroll
    for (int i = 0; i < 16; i++) {
        vals[i] = __expf(vals[i] - m);
        s += vals[i];
    }
#pragma unroll
    for (int o = 16; o; o >>= 1) s += __shfl_xor_sync(0xffffffffu, s, o);
    if ((t & 31) == 0) shsum[t >> 5] = s;
    __syncthreads();
    s = 0.f;
#pragma unroll
    for (int w = 0; w < 8; w++) s += shsum[w];

    const float inv = 1.f / s;
#pragma unroll
    for (int i = 0; i < 16; i++) p[t + i * 256] = vals[i] * inv;
}

// -------------------- Generic batched SGEMM (f32x2 FMA) ----------------------
// C[m,n] = scale * sum_k A(m,k) * B(k,n)  (+ bias[m]) (+ resid[m,n])
//   TA=false: A row-major [M x K]   | TA=true: A stored [K x M] (i.e. A^T)
//   TB=false: B row-major [K x N]   | TB=true: B stored [N x K] (i.e. B^T)
// BM=BN=128, BK=8, 256 threads, 8x8 per thread; acc packed as f32x2 pairs.
template<bool TA, bool TB>
__global__ __launch_bounds__(256)
void gemm_kernel(const float* __restrict__ A, const float* __restrict__ B,
                 float* __restrict__ Cout, int M, int N, int K,
                 size_t sA, size_t sB, size_t sC,
                 const float* __restrict__ bias,
                 const float* __restrict__ resid, size_t sR,
                 float scale)
{
    constexpr int BM = 128, BN = 128, BK = 8, TM = 8;
    __shared__ float As[BK][BM];
    __shared__ float Bs[BK][BN];

    const int zb = blockIdx.z;
    A    += (size_t)zb * sA;
    B    += (size_t)zb * sB;
    Cout += (size_t)zb * sC;

    const int bm = blockIdx.y * BM;
    const int bn = blockIdx.x * BN;
    const int tid = threadIdx.x;
    const int tx = tid & 15;   // 16 cols of threads
    const int ty = tid >> 4;   // 16 rows of threads

    u64 acc[TM][4];
#pragma unroll
    for (int i = 0; i < TM; i++)
#pragma unroll
        for (int j = 0; j < 4; j++) acc[i][j] = 0ull;

    for (int k0 = 0; k0 < K; k0 += BK) {
#pragma unroll
        for (int l = 0; l < 4; l++) {
            const int idx = tid + l * 256;  // 1024 elems per tile
            if (TA) {
                const int kk = idx >> 7, mm = idx & 127;
                As[kk][mm] = A[(size_t)(k0 + kk) * M + (bm + mm)];
            } else {
                const int mm = idx >> 3, kk = idx & 7;
                As[kk][mm] = A[(size_t)(bm + mm) * K + (k0 + kk)];
            }
            if (TB) {
                const int nn = idx >> 3, kk = idx & 7;
                Bs[kk][nn] = B[(size_t)(bn + nn) * K + (k0 + kk)];
            } else {
                const int kk = idx >> 7, nn = idx & 127;
                Bs[kk][nn] = B[(size_t)(k0 + kk) * N + (bn + nn)];
            }
        }
        __syncthreads();

#pragma unroll
        for (int kk = 0; kk < BK; kk++) {
            const float4 a0 = *reinterpret_cast<const float4*>(&As[kk][ty * 8]);
            const float4 a1 = *reinterpret_cast<const float4*>(&As[kk][ty * 8 + 4]);
            const ulonglong2* bp2 =
                reinterpret_cast<const ulonglong2*>(&Bs[kk][tx * 8]);
            const ulonglong2 bb0 = bp2[0];
            const ulonglong2 bb1 = bp2[1];

            u64 av[8];
            av[0] = pack_dup(a0.x); av[1] = pack_dup(a0.y);
            av[2] = pack_dup(a0.z); av[3] = pack_dup(a0.w);
            av[4] = pack_dup(a1.x); av[5] = pack_dup(a1.y);
            av[6] = pack_dup(a1.z); av[7] = pack_dup(a1.w);
            u64 bv[4];
            bv[0] = bb0.x; bv[1] = bb0.y; bv[2] = bb1.x; bv[3] = bb1.y;

#pragma unroll
            for (int i = 0; i < 8; i++)
#pragma unroll
                for (int j = 0; j < 4; j++)
                    fma2(acc[i][j], av[i], bv[j]);
        }
        __syncthreads();
    }

    // epilogue: scale, bias, residual
#pragma unroll
    for (int i = 0; i < TM; i++) {
        const int m = bm + ty * TM + i;
        const float bi = bias ? bias[m] : 0.f;
        const size_t off = (size_t)m * N + bn + tx * 8;
#pragma unroll
        for (int j = 0; j < 4; j++) {
            const float2 vv = unpack2(acc[i][j]);
            float o0 = vv.x * scale + bi;
            float o1 = vv.y * scale + bi;
            if (resid) {
                const float* rp = resid + (size_t)blockIdx.z * sR;
                o0 += rp[off + 2 * j];
                o1 += rp[off + 2 * j + 1];
            }
            *reinterpret_cast<float2*>(&Cout[off + 2 * j]) = make_float2(o0, o1);
        }
    }
}

// -------------------- launch ------------------------------------------------
extern "C" void kernel_launch(void* const* d_in, const int* in_sizes, int n_in,
                              void* d_out, int out_size)
{
    using namespace cfg;
    (void)in_sizes; (void)n_in; (void)out_size;

    const float* x     = (const float*)d_in[0];
    const float* gamma = (const float*)d_in[1];
    const float* beta  = (const float*)d_in[2];
    const float* Wq    = (const float*)d_in[3];
    const float* bq    = (const float*)d_in[4];
    const float* Wk    = (const float*)d_in[5];
    const float* bk    = (const float*)d_in[6];
    const float* Wv    = (const float*)d_in[7];
    const float* bv    = (const float*)d_in[8];
    const float* Wp    = (const float*)d_in[9];
    const float* bp    = (const float*)d_in[10];
    float* out = (float*)d_out;

    float *hn, *q, *k, *v, *S;
    cudaGetSymbolAddress((void**)&hn, g_hn);
    cudaGetSymbolAddress((void**)&q,  g_q);
    cudaGetSymbolAddress((void**)&k,  g_k);
    cudaGetSymbolAddress((void**)&v,  g_v);
    cudaGetSymbolAddress((void**)&S,  g_S);
    float* ha = hn;  // hn is dead after the v GEMM; reuse as attention output

    const size_t sCH = (size_t)C * HW;   // per-batch stride of [C x HW] tensors

    // 1) GroupNorm
    groupnorm_kernel<<<BATCH * NG, 512>>>(x, gamma, beta, hn);

    // 2) q, k, v = W @ hn + b   (M=C, N=HW, K=C), weights shared across batch
    dim3 gQKV(HW / 128, C / 128, BATCH);
    gemm_kernel<false, false><<<gQKV, 256>>>(Wq, hn, q, C, HW, C,
                                             0, sCH, sCH, bq, nullptr, 0, 1.f);
    gemm_kernel<false, false><<<gQKV, 256>>>(Wk, hn, k, C, HW, C,
                                             0, sCH, sCH, bk, nullptr, 0, 1.f);
    gemm_kernel<false, false><<<gQKV, 256>>>(Wv, hn, v, C, HW, C,
                                             0, sCH, sCH, bv, nullptr, 0, 1.f);

    // 3-5) attention core, one batch at a time (S is a single-batch buffer
    //      that stays L2-resident across the three kernels)
    dim3 gS(HW / 128, HW / 128, 1);
    dim3 gAV(HW / 128, C / 128, 1);
    for (int b = 0; b < BATCH; b++) {
        const float* qb = q + (size_t)b * sCH;
        const float* kb = k + (size_t)b * sCH;
        const float* vb = v + (size_t)b * sCH;
        float*       hb = ha + (size_t)b * sCH;

        // S[i,j] = (1/sqrt(C)) * sum_c q[c,i] k[c,j]  (M=N=HW, K=C; A = q^T)
        gemm_kernel<true, false><<<gS, 256>>>(qb, kb, S, HW, HW, C,
                                              0, 0, 0, nullptr, nullptr, 0,
                                              SCALE);
        // softmax over j (rows of S)
        softmax_kernel<<<HW, 256>>>(S);
        // ha[c,i] = sum_j v[c,j] S[i,j]   (M=C, N=HW, K=HW; B = S^T)
        gemm_kernel<false, true><<<gAV, 256>>>(vb, S, hb, C, HW, HW,
                                               0, 0, 0, nullptr, nullptr, 0,
                                               1.f);
    }

    // 6) out = x + Wp @ ha + bp
    gemm_kernel<false, false><<<gQKV, 256>>>(Wp, ha, out, C, HW, C,
                                             0, sCH, sCH, bp, x, sCH, 1.f);
}

// round 7
// speedup vs baseline: 5.6456x; 5.6456x over previous
#include <cuda_runtime.h>
#include <cstdint>

// ============================================================================
// AttentionBlock via mma.sync tf32 (baseline PTX target: harness compiles at
// .target sm_103 — tcgen05/.kind::tf32 are sm_103a-only and unavailable).
//
//   GroupNorm (writes transposed hnT, tf32-rounded)
//   qT = hnT·Wq^T, kT = hnT·Wk^T   (tf32-rounded out)
//   v  = Wv·hnT^T                  (tf32-rounded out)
//   S  = scale·(qT·kT^T)  -> softmax rows (tf32-rounded out)
//   haT = P·v^T                    (tf32-rounded out)
//   out = x + Wp·haT^T + bp
//
// All GEMMs: D[M,N] = A[M,K]·B[N,K]^T, both K-major -> mma .row.col directly.
// Operands pre-rounded to tf32 (rna) so the MMA's tf32 truncation is exact.
// ============================================================================

namespace cfg {
constexpr int BATCH = 8;
constexpr int C     = 512;
constexpr int HW    = 4096;
constexpr int NG    = 32;
constexpr int CPG   = C / NG;      // 16
constexpr float EPS   = 1e-5f;
constexpr float SCALE = 0.04419417382415922f;  // 1/sqrt(512)

constexpr size_t SZ_CH = (size_t)BATCH * C * HW;   // 64 MB
constexpr size_t SZ_S1 = (size_t)HW * HW;          // 64 MB (one batch)
}

// -------------------- scratch (static globals, <=64MB each) -----------------
__device__ float g_hnT[cfg::SZ_CH];   // [B, HW, C]; reused as haT later
__device__ float g_qT [cfg::SZ_CH];   // [B, HW, C]
__device__ float g_kT [cfg::SZ_CH];   // [B, HW, C]
__device__ float g_v  [cfg::SZ_CH];   // [B, C, HW]
__device__ float g_S  [cfg::SZ_S1];   // [HW, HW] one batch
__device__ float g_W  [4][cfg::C * cfg::C];  // tf32-rounded Wq,Wk,Wv,Wp

// -------------------- helpers ------------------------------------------------
__device__ __forceinline__ float tf32r(float x) {
    uint32_t u;
    asm("cvt.rna.tf32.f32 %0, %1;" : "=r"(u) : "f"(x));
    return __uint_as_float(u);
}
__device__ __forceinline__ uint32_t smem_u32(const void* p) {
    uint32_t a;
    asm("{ .reg .u64 t; cvta.to.shared.u64 t, %1; cvt.u32.u64 %0, t; }"
        : "=r"(a) : "l"(p));
    return a;
}
__device__ __forceinline__ void cp16(uint32_t dst, const void* src) {
    asm volatile("cp.async.cg.shared.global [%0], [%1], 16;"
                 :: "r"(dst), "l"(src));
}
__device__ __forceinline__ void cp_commit() {
    asm volatile("cp.async.commit_group;" ::: "memory");
}
template<int N> __device__ __forceinline__ void cp_wait() {
    asm volatile("cp.async.wait_group %0;" :: "n"(N) : "memory");
}
__device__ __forceinline__ void mma_tf32(float* d, const uint32_t* a,
                                         const uint32_t* b) {
    asm volatile(
        "mma.sync.aligned.m16n8k8.row.col.f32.tf32.tf32.f32 "
        "{%0,%1,%2,%3}, {%4,%5,%6,%7}, {%8,%9}, {%0,%1,%2,%3};"
        : "+f"(d[0]), "+f"(d[1]), "+f"(d[2]), "+f"(d[3])
        : "r"(a[0]), "r"(a[1]), "r"(a[2]), "r"(a[3]), "r"(b[0]), "r"(b[1]));
}

// -------------------- GroupNorm -> transposed tf32 output -------------------
__global__ __launch_bounds__(512)
void groupnorm_t_kernel(const float* __restrict__ x,
                        const float* __restrict__ gamma,
                        const float* __restrict__ beta,
                        float* __restrict__ outT)
{
    using namespace cfg;
    __shared__ float shs[16], shss[16];
    const int b = blockIdx.x >> 5;
    const int g = blockIdx.x & 31;
    const size_t base = ((size_t)b * C + (size_t)g * CPG) * HW;
    const int n = CPG * HW;

    float s = 0.f, ss = 0.f;
    for (int i = threadIdx.x; i < n; i += 512) {
        float v = x[base + i];
        s += v; ss += v * v;
    }
#pragma unroll
    for (int o = 16; o; o >>= 1) {
        s  += __shfl_xor_sync(0xffffffffu, s,  o);
        ss += __shfl_xor_sync(0xffffffffu, ss, o);
    }
    const int w = threadIdx.x >> 5;
    if ((threadIdx.x & 31) == 0) { shs[w] = s; shss[w] = ss; }
    __syncthreads();
    s = 0.f; ss = 0.f;
#pragma unroll
    for (int i = 0; i < 16; i++) { s += shs[i]; ss += shss[i]; }

    const float mean = s / n;
    const float var  = ss / n - mean * mean;
    const float rstd = rsqrtf(var + EPS);

    float gm[16], bt[16];
#pragma unroll
    for (int c = 0; c < 16; c++) {
        gm[c] = gamma[g * CPG + c] * rstd;
        bt[c] = beta[g * CPG + c];
    }
    for (int hw = threadIdx.x; hw < HW; hw += 512) {
        float vals[16];
#pragma unroll
        for (int c = 0; c < 16; c++)
            vals[c] = tf32r((x[base + (size_t)c * HW + hw] - mean) * gm[c] + bt[c]);
        float4* dst = reinterpret_cast<float4*>(
            outT + ((size_t)b * HW + hw) * C + g * CPG);
#pragma unroll
        for (int j = 0; j < 4; j++)
            dst[j] = make_float4(vals[4*j], vals[4*j+1], vals[4*j+2], vals[4*j+3]);
    }
}

// -------------------- tf32 rounding pass (weights) ---------------------------
__global__ __launch_bounds__(256)
void round_kernel(const float* __restrict__ in, float* __restrict__ out, int n)
{
    int i = blockIdx.x * 256 + threadIdx.x;
    if (i < n) out[i] = tf32r(in[i]);
}

// -------------------- Row softmax over 4096 (tf32-rounded output) -----------
__global__ __launch_bounds__(256)
void softmax_kernel(float* __restrict__ S)
{
    using namespace cfg;
    __shared__ float shm[8], shsum[8];
    float* p = S + blockIdx.x * (size_t)HW;
    const int t = threadIdx.x;

    float vals[16];
    float m = -3.4e38f;
#pragma unroll
    for (int i = 0; i < 16; i++) {
        vals[i] = p[t + i * 256];
        m = fmaxf(m, vals[i]);
    }
#pragma unroll
    for (int o = 16; o; o >>= 1) m = fmaxf(m, __shfl_xor_sync(0xffffffffu, m, o));
    if ((t & 31) == 0) shm[t >> 5] = m;
    __syncthreads();
    m = shm[0];
#pragma unroll
    for (int w = 1; w < 8; w++) m = fmaxf(m, shm[w]);

    float s = 0.f;
#pragma unroll
    for (int i = 0; i < 16; i++) {
        vals[i] = __expf(vals[i] - m);
        s += vals[i];
    }
#pragma unroll
    for (int o = 16; o; o >>= 1) s += __shfl_xor_sync(0xffffffffu, s, o);
    if ((t & 31) == 0) shsum[t >> 5] = s;
    __syncthreads();
    s = 0.f;
#pragma unroll
    for (int w = 0; w < 8; w++) s += shsum[w];

    const float inv = 1.f / s;
#pragma unroll
    for (int i = 0; i < 16; i++) p[t + i * 256] = tf32r(vals[i] * inv);
}

// -------------------- mma.sync tf32 GEMM: D = scale*A·B^T (+bias)(+resid) ---
// A [M,K] row-major, B [N,K] row-major, D [M,N]. Tile 128x128x32, 256 thr.
// 8 warps in 2x4: warp tile 64 (m) x 32 (n); per warp 4x4 m16n8k8 fragments.
// SMEM rows are 32 floats (128B); swizzle: col_byte ^= (row&7)<<4.
namespace mg {
constexpr int BM = 128, BN = 128, BK = 32;
constexpr int STAGE_BYTES = (BM + BN) * BK * 4;        // 32 KB
constexpr int SMEM_BYTES  = 2 * STAGE_BYTES;           // 64 KB
}

__global__ __launch_bounds__(256)
void mma_gemm(const float* __restrict__ A, const float* __restrict__ B,
              float* __restrict__ D, int M, int N, int K,
              size_t sA, size_t sB, size_t sD,
              const float* __restrict__ bias, int bias_mode,  // 0 none,1 [m],2 [n]
              const float* __restrict__ resid, size_t sR,
              float scale, int round_out)
{
    using namespace mg;
    extern __shared__ char smem[];
    const uint32_t sbase = smem_u32(smem);

    const int z = blockIdx.z;
    A += (size_t)z * sA;
    B += (size_t)z * sB;
    D += (size_t)z * sD;

    const int bm = blockIdx.y * BM;
    const int bn = blockIdx.x * BN;
    const int tid = threadIdx.x;
    const int wid = tid >> 5, lid = tid & 31;
    const int wm = wid >> 2;           // 0..1  (64 rows each)
    const int wn = wid & 3;            // 0..3  (32 cols each)
    const int grp = lid >> 2, thr = lid & 3;
    const int NC = K / BK;

    // ---- load geometry: 4 chunks (16B) per tile per thread ----
    int rowA[4], rowB[4];
    uint32_t dstA[4], dstB[4];
    const float* srcA[4];
    const float* srcB[4];
#pragma unroll
    for (int l = 0; l < 4; l++) {
        const int c = tid + l * 256;   // 0..1023
        const int row = c >> 3, u = c & 7;
        const uint32_t sw = row * 128 + ((u * 16) ^ ((row & 7) << 4));
        rowA[l] = row; rowB[l] = row;
        dstA[l] = sbase + sw;
        dstB[l] = sbase + BM * BK * 4 + sw;
        srcA[l] = A + (size_t)(bm + row) * K + u * 4;
        srcB[l] = B + (size_t)(bn + row) * K + u * 4;
    }

    auto load_chunk = [&](int kc, int st) {
        const uint32_t so = st * STAGE_BYTES;
        const int ko = kc * BK;
#pragma unroll
        for (int l = 0; l < 4; l++) cp16(dstA[l] + so, srcA[l] + ko);
#pragma unroll
        for (int l = 0; l < 4; l++) cp16(dstB[l] + so, srcB[l] + ko);
        cp_commit();
    };

    float acc[4][4][4];
#pragma unroll
    for (int i = 0; i < 4; i++)
#pragma unroll
        for (int j = 0; j < 4; j++)
#pragma unroll
            for (int r = 0; r < 4; r++) acc[i][j][r] = 0.f;

    load_chunk(0, 0);
    load_chunk(1, 1);

    const uint32_t xorv = (uint32_t)(grp << 4);  // (row&7)<<4; rows below are grp mod 8

    for (int kc = 0; kc < NC; kc++) {
        const int st = kc & 1;
        if (kc < NC - 1) cp_wait<1>(); else cp_wait<0>();
        __syncthreads();

        const char* Abase = smem + st * STAGE_BYTES;
        const char* Bbase = Abase + BM * BK * 4;

#pragma unroll
        for (int ks = 0; ks < BK / 8; ks++) {
            const uint32_t c0 = (uint32_t)((ks * 8 + thr) * 4) ^ xorv;
            const uint32_t c1 = (uint32_t)((ks * 8 + thr + 4) * 4) ^ xorv;

            uint32_t a[4][4];
#pragma unroll
            for (int mt = 0; mt < 4; mt++) {
                const int r0 = wm * 64 + mt * 16 + grp;
                a[mt][0] = *(const uint32_t*)(Abase + r0 * 128 + c0);
                a[mt][1] = *(const uint32_t*)(Abase + (r0 + 8) * 128 + c0);
                a[mt][2] = *(const uint32_t*)(Abase + r0 * 128 + c1);
                a[mt][3] = *(const uint32_t*)(Abase + (r0 + 8) * 128 + c1);
            }
            uint32_t b[4][2];
#pragma unroll
            for (int nt = 0; nt < 4; nt++) {
                const int rB = wn * 32 + nt * 8 + grp;
                b[nt][0] = *(const uint32_t*)(Bbase + rB * 128 + c0);
                b[nt][1] = *(const uint32_t*)(Bbase + rB * 128 + c1);
            }
#pragma unroll
            for (int mt = 0; mt < 4; mt++)
#pragma unroll
                for (int nt = 0; nt < 4; nt++)
                    mma_tf32(acc[mt][nt], a[mt], b[nt]);
        }
        __syncthreads();
        if (kc + 2 < NC) load_chunk(kc + 2, st);
    }

    // ---- epilogue: scale, bias, residual, optional tf32 round ----
#pragma unroll
    for (int mt = 0; mt < 4; mt++) {
#pragma unroll
        for (int half = 0; half < 2; half++) {
            const int m = bm + wm * 64 + mt * 16 + grp + half * 8;
            const float biasM = (bias_mode == 1) ? bias[m] : 0.f;
#pragma unroll
            for (int nt = 0; nt < 4; nt++) {
                const int n = bn + wn * 32 + nt * 8 + 2 * thr;
                float v0 = acc[mt][nt][half * 2 + 0] * scale;
                float v1 = acc[mt][nt][half * 2 + 1] * scale;
                if (bias_mode == 1) { v0 += biasM; v1 += biasM; }
                else if (bias_mode == 2) { v0 += bias[n]; v1 += bias[n + 1]; }
                const size_t off = (size_t)m * N + n;
                if (resid) {
                    const float* rp = resid + (size_t)z * sR;
                    v0 += rp[off]; v1 += rp[off + 1];
                }
                if (round_out) { v0 = tf32r(v0); v1 = tf32r(v1); }
                *reinterpret_cast<float2*>(D + off) = make_float2(v0, v1);
            }
        }
    }
}

// -------------------- launch ------------------------------------------------
extern "C" void kernel_launch(void* const* d_in, const int* in_sizes, int n_in,
                              void* d_out, int out_size)
{
    using namespace cfg;
    (void)in_sizes; (void)n_in; (void)out_size;

    const float* x     = (const float*)d_in[0];
    const float* gamma = (const float*)d_in[1];
    const float* beta  = (const float*)d_in[2];
    const float* Wq    = (const float*)d_in[3];
    const float* bq    = (const float*)d_in[4];
    const float* Wk    = (const float*)d_in[5];
    const float* bk    = (const float*)d_in[6];
    const float* Wv    = (const float*)d_in[7];
    const float* bv    = (const float*)d_in[8];
    const float* Wp    = (const float*)d_in[9];
    const float* bp    = (const float*)d_in[10];
    float* out = (float*)d_out;

    float *hnT, *qT, *kT, *v, *S, *W;
    cudaGetSymbolAddress((void**)&hnT, g_hnT);
    cudaGetSymbolAddress((void**)&qT,  g_qT);
    cudaGetSymbolAddress((void**)&kT,  g_kT);
    cudaGetSymbolAddress((void**)&v,   g_v);
    cudaGetSymbolAddress((void**)&S,   g_S);
    cudaGetSymbolAddress((void**)&W,   g_W);
    float* rWq = W;
    float* rWk = W + (size_t)C * C;
    float* rWv = W + 2 * (size_t)C * C;
    float* rWp = W + 3 * (size_t)C * C;
    float* haT = hnT;   // hnT dead after q/k/v GEMMs

    cudaFuncSetAttribute(mma_gemm, cudaFuncAttributeMaxDynamicSharedMemorySize,
                         mg::SMEM_BYTES);

    const size_t sT = (size_t)HW * C;
    const int    WN = C * C;

    // 1) GroupNorm -> hnT [B, HW, C] (tf32)
    groupnorm_t_kernel<<<BATCH * NG, 512>>>(x, gamma, beta, hnT);

    // 2) round weights to tf32
    round_kernel<<<(WN + 255) / 256, 256>>>(Wq, rWq, WN);
    round_kernel<<<(WN + 255) / 256, 256>>>(Wk, rWk, WN);
    round_kernel<<<(WN + 255) / 256, 256>>>(Wv, rWv, WN);
    round_kernel<<<(WN + 255) / 256, 256>>>(Wp, rWp, WN);

    // 3) qT = hnT·Wq^T + bq[n], kT likewise   (M=HW, N=C, K=C)
    dim3 gT(C / 128, HW / 128, BATCH);
    mma_gemm<<<gT, 256, mg::SMEM_BYTES>>>(hnT, rWq, qT, HW, C, C,
                                          sT, 0, sT, bq, 2, nullptr, 0, 1.f, 1);
    mma_gemm<<<gT, 256, mg::SMEM_BYTES>>>(hnT, rWk, kT, HW, C, C,
                                          sT, 0, sT, bk, 2, nullptr, 0, 1.f, 1);

    // 4) v = Wv·hnT^T + bv[m]   (M=C, N=HW, K=C) -> [B, C, HW]
    dim3 gV(HW / 128, C / 128, BATCH);
    mma_gemm<<<gV, 256, mg::SMEM_BYTES>>>(rWv, hnT, v, C, HW, C,
                                          0, sT, sT, bv, 1, nullptr, 0, 1.f, 1);

    // 5) per-batch attention core (S stays L2-resident across 3 kernels)
    dim3 gS(HW / 128, HW / 128, 1);
    dim3 gAV(C / 128, HW / 128, 1);
    for (int b = 0; b < BATCH; b++) {
        const float* qb = qT + (size_t)b * sT;
        const float* kb = kT + (size_t)b * sT;
        const float* vb = v  + (size_t)b * sT;
        float*       hb = haT + (size_t)b * sT;

        // S = scale·(qT·kT^T)   (M=N=HW, K=C)
        mma_gemm<<<gS, 256, mg::SMEM_BYTES>>>(qb, kb, S, HW, HW, C,
                                              0, 0, 0, nullptr, 0, nullptr, 0,
                                              SCALE, 0);
        softmax_kernel<<<HW, 256>>>(S);
        // haT = P·v^T   (M=HW, N=C, K=HW)
        mma_gemm<<<gAV, 256, mg::SMEM_BYTES>>>(S, vb, hb, HW, C, HW,
                                               0, 0, 0, nullptr, 0, nullptr, 0,
                                               1.f, 1);
    }

    // 6) out = x + Wp·haT^T + bp[m]   (M=C, N=HW, K=C)
    mma_gemm<<<gV, 256, mg::SMEM_BYTES>>>(rWp, haT, out, C, HW, C,
                                          0, sT, sT, bp, 1, x, sT, 1.f, 0);
}